// round 5
// baseline (speedup 1.0000x reference)
#include <cuda_runtime.h>

// maxF1 loss: input/target [B=16, C=4, H=512, W=512] float32.
// loss = mean_c (1 - max_k F1_c(k)),  F1 = 2*TP/(P+PP) over 1000 thresholds.
//
// Single fused kernel:
//   - per-class 1001-bin histogram of idx = ceil(x*999), 8-way warp-private
//     shared histograms (u32 packed count|y<<16), flushed to global atomics
//   - last block (global ticket) scans the histograms, computes F1 max and
//     the loss, then re-zeroes global state for the next graph replay.

#define NTHRESH 1000
#define NBINS   (NTHRESH + 1)
#define NBINSP  1004                   // padded row (16B-aligned uint4 loads)
#define CCLS    4
#define BB      16
#define HW      (512 * 512)
#define N_PER_CLASS (BB * HW)          // 4194304
#define PLANES  (BB * CCLS)            // 64
#define SLICES  16
#define NBLOCKS (PLANES * SLICES)      // 1024
#define HTHREADS 256
#define NCOPY   8                      // one shared histogram per warp
#define ELEMS_PER_BLOCK (HW / SLICES)  // 16384
#define N4      (ELEMS_PER_BLOCK / 4)  // 4096

__device__ unsigned int g_hist[CCLS][NBINSP];  // count | y<<16 (pad stays 0)
__device__ unsigned int g_ticket;

__global__ __launch_bounds__(HTHREADS) void fused_kernel(
    const float* __restrict__ x, const float* __restrict__ y,
    float* __restrict__ out)
{
    __shared__ unsigned int s_hist[NCOPY][NBINS];
    __shared__ unsigned long long s_w[NCOPY];
    __shared__ float s_m[NCOPY];
    __shared__ unsigned int s_last;

    const int tid = threadIdx.x;
    const int wid = tid >> 5;
    const int lane = tid & 31;

#pragma unroll
    for (int k = tid; k < NCOPY * NBINS; k += HTHREADS)
        ((unsigned int*)s_hist)[k] = 0u;
    __syncthreads();

    unsigned int* __restrict__ hb = s_hist[wid];

    const int plane = blockIdx.x >> 4;           // / SLICES
    const int slice = blockIdx.x & (SLICES - 1);
    const int cls = plane & (CCLS - 1);          // [B,C,H,W]: plane = b*C + c
    const long long base =
        (long long)plane * HW + (long long)slice * ELEMS_PER_BLOCK;

    const float4* __restrict__ x4 = (const float4*)(x + base);
    const float4* __restrict__ y4 = (const float4*)(y + base);

#pragma unroll 4
    for (int i = tid; i < N4; i += HTHREADS) {
        float4 xv = x4[i];
        float4 yv = y4[i];
#pragma unroll
        for (int j = 0; j < 4; j++) {
            // idx = #{k : k/999 < xs} = ceil(xs*999); x in [0,1) -> idx <= 999
            int idx = __float2int_ru((&xv.x)[j] * 999.0f);
            // y in {0.0f,1.0f}: (bits>>13)&0x10000 == y<<16
            unsigned int yb = __float_as_uint((&yv.x)[j]);
            atomicAdd(&hb[idx], ((yb >> 13) & 0x10000u) | 1u);
        }
    }
    __syncthreads();

    for (int k = tid; k < NBINS; k += HTHREADS) {
        unsigned int v = 0;
#pragma unroll
        for (int c = 0; c < NCOPY; c++) v += s_hist[c][k];
        atomicAdd(&g_hist[cls][k], v);
    }
    __syncthreads();

    // ---- ticket: last block to arrive runs the epilogue ----
    if (tid == 0) {
        __threadfence();
        s_last = atomicAdd(&g_ticket, 1u);
    }
    __syncthreads();
    if (s_last != NBLOCKS - 1) return;
    __threadfence();

    // ---- epilogue: scan + F1 max + loss, 256 threads, 4 bins/thread ----
    float loss = 0.0f;
#pragma unroll
    for (int c = 0; c < CCLS; c++) {
        const int k0 = tid * 4;
        unsigned long long v[4];
        if (k0 < NBINSP) {
            uint4 hv = *(const uint4*)&g_hist[c][k0];
#pragma unroll
            for (int j = 0; j < 4; j++) {
                unsigned int h = (&hv.x)[j];
                v[j] = (unsigned long long)(h & 0xffffu) |
                       ((unsigned long long)(h >> 16) << 32);
            }
        } else {
            v[0] = v[1] = v[2] = v[3] = 0ULL;
        }
        // serial inclusive within thread
        v[1] += v[0]; v[2] += v[1]; v[3] += v[2];
        unsigned long long tot = v[3];
        // warp inclusive scan of thread totals
        unsigned long long incl = tot;
#pragma unroll
        for (int o = 1; o < 32; o <<= 1) {
            unsigned long long t = __shfl_up_sync(0xffffffffu, incl, o);
            if (lane >= o) incl += t;
        }
        if (lane == 31) s_w[wid] = incl;
        __syncthreads();
        if (tid == 0) {
            unsigned long long acc = 0ULL;
#pragma unroll
            for (int w = 0; w < NCOPY; w++) {
                acc += s_w[w];
                s_w[w] = acc;   // inclusive warp totals
            }
        }
        __syncthreads();
        unsigned long long off =
            (incl - tot) + (wid ? s_w[wid - 1] : 0ULL);
        unsigned int P = (unsigned int)(s_w[NCOPY - 1] >> 32);

        float fmx = 0.0f;
#pragma unroll
        for (int j = 0; j < 4; j++) {
            int k = k0 + j;
            if (k < NTHRESH) {
                unsigned long long cum = off + v[j];
                unsigned int cumc = (unsigned int)(cum & 0xffffffffULL);
                unsigned int cumy = (unsigned int)(cum >> 32);
                unsigned int TP = P - cumy;
                unsigned int PP = (unsigned int)N_PER_CLASS - cumc;
                unsigned int den = P + PP;   // 2*(TP + 0.5*(FN+FP))
                float f1 = (den == 0u) ? 0.0f
                                       : (2.0f * (float)TP) / (float)den;
                fmx = fmaxf(fmx, f1);
            }
        }
#pragma unroll
        for (int o = 16; o; o >>= 1)
            fmx = fmaxf(fmx, __shfl_xor_sync(0xffffffffu, fmx, o));
        if (lane == 0) s_m[wid] = fmx;
        __syncthreads();
        if (tid == 0) {
            float m = s_m[0];
#pragma unroll
            for (int w = 1; w < NCOPY; w++) m = fmaxf(m, s_m[w]);
            loss += 1.0f - m;
        }
        __syncthreads();  // s_w / s_m reuse next class
    }

    // re-zero global state for the next replay (statics start zeroed)
    for (int k = tid; k < CCLS * NBINSP; k += HTHREADS)
        ((unsigned int*)g_hist)[k] = 0u;
    if (tid == 0) {
        g_ticket = 0u;
        out[0] = loss / (float)CCLS;
    }
}

extern "C" void kernel_launch(void* const* d_in, const int* in_sizes, int n_in,
                              void* d_out, int out_size) {
    const float* x = (const float*)d_in[0];   // input
    const float* y = (const float*)d_in[1];   // target
    (void)in_sizes; (void)n_in; (void)out_size;

    fused_kernel<<<NBLOCKS, HTHREADS>>>(x, y, (float*)d_out);
}

// round 6
// speedup vs baseline: 1.3044x; 1.3044x over previous
#include <cuda_runtime.h>

// maxF1 loss: input/target [B=16, C=4, H=512, W=512] float32.
// loss = mean_c (1 - max_k F1_c(k)),  F1 = 2*TP/(P+PP) over 1000 thresholds.
//
// Single fused kernel:
//   - per-class 1001-bin histogram of idx = ceil(x*999), 4-way shared
//     histograms (u32 packed count|y<<16), flushed via global atomics
//   - last block (global ticket) scans the histograms (two u32 scans),
//     computes F1 max + loss, re-zeroes global state for the next replay.
// __launch_bounds__(256, 8) pins regs <= 32 so the mainloop keeps
// 8 blocks/SM (epilogue may spill; it runs once in one block).

#define NTHRESH 1000
#define NBINS   (NTHRESH + 1)
#define NBINSP  1004                   // padded row (16B-aligned uint4 loads)
#define CCLS    4
#define BB      16
#define HW      (512 * 512)
#define N_PER_CLASS (BB * HW)          // 4194304
#define PLANES  (BB * CCLS)            // 64
#define SLICES  16
#define NBLOCKS (PLANES * SLICES)      // 1024
#define HTHREADS 256
#define NWARPS  (HTHREADS / 32)        // 8
#define NCOPY   4
#define ELEMS_PER_BLOCK (HW / SLICES)  // 16384
#define N4      (ELEMS_PER_BLOCK / 4)  // 4096

__device__ unsigned int g_hist[CCLS][NBINSP];  // count | y<<16 (pad stays 0)
__device__ unsigned int g_ticket;

__global__ __launch_bounds__(HTHREADS, 8) void fused_kernel(
    const float* __restrict__ x, const float* __restrict__ y,
    float* __restrict__ out)
{
    __shared__ unsigned int s_hist[NCOPY][NBINS];
    __shared__ unsigned int s_wc[NWARPS], s_wy[NWARPS];
    __shared__ float s_m[NWARPS];
    __shared__ unsigned int s_last;

    const int tid = threadIdx.x;
    const int wid = tid >> 5;
    const int lane = tid & 31;

#pragma unroll
    for (int k = tid; k < NCOPY * NBINS; k += HTHREADS)
        ((unsigned int*)s_hist)[k] = 0u;
    __syncthreads();

    unsigned int* __restrict__ hb = s_hist[wid & (NCOPY - 1)];

    const int plane = blockIdx.x >> 4;           // / SLICES
    const int slice = blockIdx.x & (SLICES - 1);
    const int cls = plane & (CCLS - 1);          // [B,C,H,W]: plane = b*C + c
    const long long base =
        (long long)plane * HW + (long long)slice * ELEMS_PER_BLOCK;

    const float4* __restrict__ x4 = (const float4*)(x + base);
    const float4* __restrict__ y4 = (const float4*)(y + base);

#pragma unroll 4
    for (int i = tid; i < N4; i += HTHREADS) {
        float4 xv = x4[i];
        float4 yv = y4[i];
#pragma unroll
        for (int j = 0; j < 4; j++) {
            // idx = #{k : k/999 < xs} = ceil(xs*999); x in [0,1) -> idx <= 999
            int idx = __float2int_ru((&xv.x)[j] * 999.0f);
            // y in {0.0f,1.0f}: (bits>>13)&0x10000 == y<<16
            unsigned int yb = __float_as_uint((&yv.x)[j]);
            atomicAdd(&hb[idx], ((yb >> 13) & 0x10000u) | 1u);
        }
    }
    __syncthreads();

    for (int k = tid; k < NBINS; k += HTHREADS) {
        unsigned int v = s_hist[0][k] + s_hist[1][k] +
                         s_hist[2][k] + s_hist[3][k];
        atomicAdd(&g_hist[cls][k], v);
    }

    // ---- ticket: last block to arrive runs the epilogue ----
    if (tid == 0) {
        __threadfence();
        s_last = atomicAdd(&g_ticket, 1u);
    }
    __syncthreads();
    if (s_last != NBLOCKS - 1) return;
    __threadfence();

    // ---- epilogue: scan + F1 max + loss, 256 threads, 4 bins/thread ----
    float loss = 0.0f;
#pragma unroll 1
    for (int c = 0; c < CCLS; c++) {
        const int k0 = tid * 4;
        unsigned int vc[4], vy[4];
        if (k0 < NBINSP) {
            uint4 hv = *(const uint4*)&g_hist[c][k0];
#pragma unroll
            for (int j = 0; j < 4; j++) {
                unsigned int h = (&hv.x)[j];
                vc[j] = h & 0xffffu;
                vy[j] = h >> 16;
            }
        } else {
            vc[0] = vc[1] = vc[2] = vc[3] = 0u;
            vy[0] = vy[1] = vy[2] = vy[3] = 0u;
        }
        // serial inclusive within thread
        vc[1] += vc[0]; vc[2] += vc[1]; vc[3] += vc[2];
        vy[1] += vy[0]; vy[2] += vy[1]; vy[3] += vy[2];
        unsigned int tc = vc[3], ty = vy[3];
        // warp inclusive scan of thread totals (two independent u32 chains)
        unsigned int ic = tc, iy = ty;
#pragma unroll
        for (int o = 1; o < 32; o <<= 1) {
            unsigned int a = __shfl_up_sync(0xffffffffu, ic, o);
            unsigned int b = __shfl_up_sync(0xffffffffu, iy, o);
            if (lane >= o) { ic += a; iy += b; }
        }
        if (lane == 31) { s_wc[wid] = ic; s_wy[wid] = iy; }
        __syncthreads();
        if (tid == 0) {
            unsigned int ac = 0u, ay = 0u;
#pragma unroll
            for (int w = 0; w < NWARPS; w++) {
                ac += s_wc[w]; ay += s_wy[w];
                s_wc[w] = ac;  s_wy[w] = ay;  // inclusive warp totals
            }
        }
        __syncthreads();
        unsigned int offc = (ic - tc) + (wid ? s_wc[wid - 1] : 0u);
        unsigned int offy = (iy - ty) + (wid ? s_wy[wid - 1] : 0u);
        unsigned int P = s_wy[NWARPS - 1];   // total positives

        float fmx = 0.0f;
#pragma unroll
        for (int j = 0; j < 4; j++) {
            int k = k0 + j;
            if (k < NTHRESH) {
                unsigned int TP = P - (offy + vy[j]);
                unsigned int PP = (unsigned int)N_PER_CLASS - (offc + vc[j]);
                unsigned int den = P + PP;   // 2*(TP + 0.5*(FN+FP))
                float f1 = (den == 0u) ? 0.0f
                                       : (2.0f * (float)TP) / (float)den;
                fmx = fmaxf(fmx, f1);
            }
        }
#pragma unroll
        for (int o = 16; o; o >>= 1)
            fmx = fmaxf(fmx, __shfl_xor_sync(0xffffffffu, fmx, o));
        if (lane == 0) s_m[wid] = fmx;
        __syncthreads();
        if (tid == 0) {
            float m = s_m[0];
#pragma unroll
            for (int w = 1; w < NWARPS; w++) m = fmaxf(m, s_m[w]);
            loss += 1.0f - m;
        }
        __syncthreads();  // s_wc/s_wy/s_m reuse next class
    }

    // re-zero global state for the next replay (statics start zeroed)
    for (int k = tid; k < CCLS * NBINSP; k += HTHREADS)
        ((unsigned int*)g_hist)[k] = 0u;
    if (tid == 0) {
        g_ticket = 0u;
        out[0] = loss / (float)CCLS;
    }
}

extern "C" void kernel_launch(void* const* d_in, const int* in_sizes, int n_in,
                              void* d_out, int out_size) {
    const float* x = (const float*)d_in[0];   // input
    const float* y = (const float*)d_in[1];   // target
    (void)in_sizes; (void)n_in; (void)out_size;

    fused_kernel<<<NBLOCKS, HTHREADS>>>(x, y, (float*)d_out);
}